// round 7
// baseline (speedup 1.0000x reference)
#include <cuda_runtime.h>
#include <cstdint>

#define HH 1024
#define WW 1024
#define WPR 32                 // 32-bit words per bitmap row
#define NF4 (HH * WW / 4)      // 262144 float4 elements
#define TPB 256                // threads per CTA

// Scratch (no allocations allowed).
// TRANSPOSED bitmap: g_bits_T[w*HH + r] = bits for columns [32w,32w+31] of row r.
__device__ uint32_t g_bits_T[WPR * HH];  // 128 KB
__device__ float    g_loss[1024];
__device__ unsigned g_sync;   // pack-phase grid barrier (self-resetting)
__device__ unsigned g_cnt;    // finalize ticket          (self-resetting)

__device__ __forceinline__ uint32_t ldcg_u32(const uint32_t* p) {
    uint32_t v;
    asm volatile("ld.global.cg.u32 %0, [%1];" : "=r"(v) : "l"(p));
    return v;
}

__device__ __forceinline__ int bit_at(int r, int c) {
    r = min(max(r, 0), HH - 1);
    c = min(max(c, 0), WW - 1);
    return (int)((ldcg_u32(&g_bits_T[(c >> 5) * HH + r]) >> (c & 31)) & 1u);
}

__global__ void __launch_bounds__(TPB) fused_kernel(const float4* __restrict__ m4,
                                                    const int*    __restrict__ pred,
                                                    float*        __restrict__ out,
                                                    int N) {
    const int tid  = threadIdx.x;
    const int cta  = blockIdx.x;
    const int lane = tid & 31;
    const int wid  = tid >> 5;

    // Prefetch this CTA's point early (overlaps DRAM latency with pack phase).
    const int p0 = __ldg(&pred[2 * cta]);
    const int p1 = __ldg(&pred[2 * cta + 1]);

    // ============================ Phase 1: pack =============================
    // Grid-stride over float4s; warp-uniform trip count (stride multiple of 32).
    {
        const int nthreads = gridDim.x * TPB;
        const uint32_t sh  = (uint32_t)((lane & 7) * 4);
#pragma unroll 8
        for (int idx = cta * TPB + tid; idx < NF4; idx += nthreads) {
            float4 v = m4[idx];
            uint32_t nib = (uint32_t)(v.x != 0.0f)
                         | ((uint32_t)(v.y != 0.0f) << 1)
                         | ((uint32_t)(v.z != 0.0f) << 2)
                         | ((uint32_t)(v.w != 0.0f) << 3);
            uint32_t b = nib << sh;
            b |= __shfl_xor_sync(0xFFFFFFFFu, b, 1);
            b |= __shfl_xor_sync(0xFFFFFFFFu, b, 2);
            b |= __shfl_xor_sync(0xFFFFFFFFu, b, 4);
            if ((lane & 7) == 0) {
                int i32 = idx >> 3;                       // word index, row-major
                g_bits_T[(i32 & 31) * HH + (i32 >> 5)] = b;   // transposed store
            }
        }
    }

    // ====================== grid barrier (spin, safe: all CTAs resident) ====
    __threadfence();
    __syncthreads();
    if (tid == 0) {
        atomicAdd(&g_sync, 1u);
        while (atomicAdd(&g_sync, 0u) < (unsigned)gridDim.x) { }
    }
    __syncthreads();

    // ============================ Phase 2: point ============================
    const bool outside_frame = (p0 < 0) | (p0 > HH) | (p1 < 0) | (p1 > WW);
    const int BIG = 1 << 20;
    int best_nd = 0x7FFFFFFF, best_dr = 0x7FFFFFFF;

    if (!outside_frame) {      // block-uniform
        const int  pcl   = min(p1, WW - 1);
        const int  w0    = pcl >> 5;                       // word containing p1 (or 31)
        const uint32_t maskL = 0xFFFFFFFFu >> (31 - (pcl & 31));
        const bool doR   = (p1 <= WW - 1);
        const uint32_t maskR = doR ? (0xFFFFFFFFu << (p1 & 31)) : 0u;

        // Batched initial loads: 4 independent rows -> MLP=4, one L2 latency.
        uint32_t W0[4];
#pragma unroll
        for (int j = 0; j < 4; ++j)
            W0[j] = ldcg_u32(&g_bits_T[w0 * HH + (tid + TPB * j)]);

#pragma unroll
        for (int j = 0; j < 4; ++j) {
            const int r = tid + TPB * j;
            int dsl = BIG, dcl = BIG, dsr = BIG, dcr = BIG;
            // ---- left (columns <= p1), starting word shared with right ----
            {
                uint32_t ms = W0[j] & maskL, mc = ~W0[j] & maskL;
                if (ms) dsl = p1 - ((w0 << 5) + 31 - __clz(ms));
                if (mc) dcl = p1 - ((w0 << 5) + 31 - __clz(mc));
                for (int ww = w0 - 1; ww >= 0 && ((dsl == BIG) | (dcl == BIG)); --ww) {
                    uint32_t word = ldcg_u32(&g_bits_T[ww * HH + r]);
                    if (dsl == BIG && word)  dsl = p1 - ((ww << 5) + 31 - __clz(word));
                    uint32_t mcw = ~word;
                    if (dcl == BIG && mcw)   dcl = p1 - ((ww << 5) + 31 - __clz(mcw));
                }
            }
            // ---- right (columns >= p1) ----
            if (doR) {
                uint32_t ms = W0[j] & maskR, mc = ~W0[j] & maskR;
                if (ms) dsr = ((w0 << 5) + __ffs(ms) - 1) - p1;
                if (mc) dcr = ((w0 << 5) + __ffs(mc) - 1) - p1;
                for (int ww = w0 + 1; ww < WPR && ((dsr == BIG) | (dcr == BIG)); ++ww) {
                    uint32_t word = ldcg_u32(&g_bits_T[ww * HH + r]);
                    if (dsr == BIG && word)  dsr = ((ww << 5) + __ffs(word) - 1) - p1;
                    uint32_t mcw = ~word;
                    if (dcr == BIG && mcw)   dcr = ((ww << 5) + __ffs(mcw) - 1) - p1;
                }
            }
            int ds = min(dsl, dsr);                       // nearest road col dist
            int dc = min(dcl, dcr);                       // nearest non-road col dist
            int dr2 = (r - p0) * (r - p0);
            if (ds < 2048) best_nd = min(best_nd, dr2 + ds * ds);
            if (dc < 2048) best_dr = min(best_dr, dr2 + dc * dc);
        }
    }

    // ---- block min-reduce over 256 threads (8 warps) ----
    __shared__ int snd[8], sdr[8];
    best_nd = __reduce_min_sync(0xFFFFFFFFu, best_nd);
    best_dr = __reduce_min_sync(0xFFFFFFFFu, best_dr);
    if (lane == 0) { snd[wid] = best_nd; sdr[wid] = best_dr; }
    __syncthreads();

    __shared__ bool isLast;
    if (tid == 0) {
        int a = snd[0], b = sdr[0];
#pragma unroll
        for (int k = 1; k < 8; ++k) { a = min(a, snd[k]); b = min(b, sdr[k]); }
        float L = 0.0f;
        if (!outside_frame) {
            // outside_road: replicate reference's validity masks exactly
            const bool rvm1 = (p0 >= 1);
            const bool rv0  = (p0 >= 1) && (p0 < HH);
            const bool cvm1 = (p1 >= 1);
            const bool cv0  = (p1 >= 1) && (p1 < WW);
            const bool outside_road =
                (rvm1 && cvm1 && bit_at(p0 - 1, p1 - 1)) ||
                (rvm1 && cv0  && bit_at(p0 - 1, p1    )) ||
                (rv0  && cvm1 && bit_at(p0,     p1 - 1)) ||
                (rv0  && cv0  && bit_at(p0,     p1    ));
            if (outside_road) {
                // exp(sqrt(min_dr)*ln2/40) - 1 == 2^(sqrt(min_dr)/40) - 1
                L = exp2f(sqrtf((float)b) * (1.0f / 40.0f)) - 1.0f;
            } else {
                L = expf(-(float)a * (1.0f / 21.7f));
            }
        }
        g_loss[cta] = L;
        __threadfence();
        unsigned prev = atomicAdd(&g_cnt, 1u);
        isLast = (prev == (unsigned)(gridDim.x - 1));
        if (isLast) __threadfence();
    }
    __syncthreads();

    // ---- last CTA: deterministic fixed-order reduction -> mean, reset ctrs ----
    if (isLast) {
        float v = 0.0f;
        for (int t = tid; t < N; t += TPB)
            v += __int_as_float((int)ldcg_u32((const uint32_t*)&g_loss[t]));
#pragma unroll
        for (int o = 16; o; o >>= 1) v += __shfl_down_sync(0xFFFFFFFFu, v, o);
        __shared__ float ws[8];
        if (lane == 0) ws[wid] = v;
        __syncthreads();
        if (tid == 0) {
            float s = 0.0f;
#pragma unroll
            for (int w = 0; w < 8; ++w) s += ws[w];
            out[0] = s / (float)N;
            g_sync = 0u;           // self-reset for next graph replay
            g_cnt  = 0u;
        }
    }
}

extern "C" void kernel_launch(void* const* d_in, const int* in_sizes, int n_in,
                              void* d_out, int out_size) {
    const float* hd_map = (const float*)d_in[0];
    const int*   pred   = (const int*)d_in[1];
    float*       out    = (float*)d_out;
    const int N = in_sizes[1] / 2;   // 128

    fused_kernel<<<N, TPB>>>((const float4*)hd_map, pred, out, N);
}

// round 8
// speedup vs baseline: 1.0711x; 1.0711x over previous
#include <cuda_runtime.h>
#include <cstdint>

#define HH 1024
#define WW 1024
#define WPR 32                 // 32-bit words per bitmap row
#define NF4 (HH * WW / 4)      // 262144 float4 elements
#define TPB 256                // threads per CTA
#define CTAS 512               // grid size (>= N; all resident: 512/148 < 4 per SM)

// Scratch (no allocations allowed).
// TRANSPOSED bitmap: g_bits_T[w*HH + r] = bits for columns [32w,32w+31] of row r.
__device__ uint32_t g_bits_T[WPR * HH];  // 128 KB
__device__ float    g_loss[1024];
__device__ unsigned g_sync;   // pack-phase grid barrier (self-resetting, see below)
__device__ unsigned g_cnt;    // finalize ticket          (self-resetting)

__device__ __forceinline__ uint32_t ldcg_u32(const uint32_t* p) {
    uint32_t v;
    asm volatile("ld.global.cg.u32 %0, [%1];" : "=r"(v) : "l"(p));
    return v;
}

__device__ __forceinline__ int bit_at(int r, int c) {
    r = min(max(r, 0), HH - 1);
    c = min(max(c, 0), WW - 1);
    return (int)((ldcg_u32(&g_bits_T[(c >> 5) * HH + r]) >> (c & 31)) & 1u);
}

__global__ void __launch_bounds__(TPB) fused_kernel(const float4* __restrict__ m4,
                                                    const int*    __restrict__ pred,
                                                    float*        __restrict__ out,
                                                    int N) {
    const int tid  = threadIdx.x;
    const int cta  = blockIdx.x;
    const int lane = tid & 31;
    const int wid  = tid >> 5;
    const bool isPointCTA = (cta < N);

    // Prefetch this CTA's point early (overlaps DRAM latency with pack phase).
    int p0 = 0, p1 = 0;
    if (isPointCTA) {
        p0 = __ldg(&pred[2 * cta]);
        p1 = __ldg(&pred[2 * cta + 1]);
    }

    // ============================ Phase 1: pack =============================
    // 512*256 = 131072 threads, 2 front-batched float4 each (exactly NF4).
    // In-flight bytes ~ 131072 * 32B = 4MB > latency-BW product -> BW-bound.
    {
        const int idx = cta * TPB + tid;               // 0 .. 131071
        const float4 va = m4[idx];
        const float4 vb = m4[idx + CTAS * TPB];        // independent load
        const uint32_t sh = (uint32_t)((lane & 7) * 4);

        uint32_t na = (uint32_t)(va.x != 0.0f)
                    | ((uint32_t)(va.y != 0.0f) << 1)
                    | ((uint32_t)(va.z != 0.0f) << 2)
                    | ((uint32_t)(va.w != 0.0f) << 3);
        uint32_t nb = (uint32_t)(vb.x != 0.0f)
                    | ((uint32_t)(vb.y != 0.0f) << 1)
                    | ((uint32_t)(vb.z != 0.0f) << 2)
                    | ((uint32_t)(vb.w != 0.0f) << 3);
        uint32_t ba = na << sh, bb = nb << sh;
        ba |= __shfl_xor_sync(0xFFFFFFFFu, ba, 1);
        bb |= __shfl_xor_sync(0xFFFFFFFFu, bb, 1);
        ba |= __shfl_xor_sync(0xFFFFFFFFu, ba, 2);
        bb |= __shfl_xor_sync(0xFFFFFFFFu, bb, 2);
        ba |= __shfl_xor_sync(0xFFFFFFFFu, ba, 4);
        bb |= __shfl_xor_sync(0xFFFFFFFFu, bb, 4);
        if ((lane & 7) == 0) {
            int ia = idx >> 3;                         // word index, row-major
            int ib = (idx + CTAS * TPB) >> 3;
            g_bits_T[(ia & 31) * HH + (ia >> 5)] = ba; // transposed stores
            g_bits_T[(ib & 31) * HH + (ib >> 5)] = bb;
        }
    }

    // ================= grid barrier (spin; all 512 CTAs resident) ===========
    __syncthreads();                 // all pack stores of this CTA issued
    if (tid == 0) {
        __threadfence();             // make stores visible before arrive
        atomicAdd(&g_sync, 1u);
        while (*(volatile unsigned*)&g_sync < (unsigned)CTAS) { }
        __threadfence();             // acquire: order subsequent loads
    }
    __syncthreads();

    // ============================ Phase 2: point ============================
    if (isPointCTA) {
        const bool outside_frame = (p0 < 0) | (p0 > HH) | (p1 < 0) | (p1 > WW);
        const int BIG = 1 << 20;
        int best_nd = 0x7FFFFFFF, best_dr = 0x7FFFFFFF;

        if (!outside_frame) {        // block-uniform
            const int  pcl   = min(p1, WW - 1);
            const int  w0    = pcl >> 5;
            const uint32_t maskL = 0xFFFFFFFFu >> (31 - (pcl & 31));
            const bool doR   = (p1 <= WW - 1);
            const uint32_t maskR = doR ? (0xFFFFFFFFu << (p1 & 31)) : 0u;

            // Batched initial loads: 4 independent rows -> MLP=4.
            uint32_t W0[4];
#pragma unroll
            for (int j = 0; j < 4; ++j)
                W0[j] = ldcg_u32(&g_bits_T[w0 * HH + (tid + TPB * j)]);

#pragma unroll
            for (int j = 0; j < 4; ++j) {
                const int r = tid + TPB * j;
                int dsl = BIG, dcl = BIG, dsr = BIG, dcr = BIG;
                // ---- left (columns <= p1) ----
                {
                    uint32_t ms = W0[j] & maskL, mc = ~W0[j] & maskL;
                    if (ms) dsl = p1 - ((w0 << 5) + 31 - __clz(ms));
                    if (mc) dcl = p1 - ((w0 << 5) + 31 - __clz(mc));
                    for (int ww = w0 - 1; ww >= 0 && ((dsl == BIG) | (dcl == BIG)); --ww) {
                        uint32_t word = ldcg_u32(&g_bits_T[ww * HH + r]);
                        if (dsl == BIG && word)  dsl = p1 - ((ww << 5) + 31 - __clz(word));
                        uint32_t mcw = ~word;
                        if (dcl == BIG && mcw)   dcl = p1 - ((ww << 5) + 31 - __clz(mcw));
                    }
                }
                // ---- right (columns >= p1) ----
                if (doR) {
                    uint32_t ms = W0[j] & maskR, mc = ~W0[j] & maskR;
                    if (ms) dsr = ((w0 << 5) + __ffs(ms) - 1) - p1;
                    if (mc) dcr = ((w0 << 5) + __ffs(mc) - 1) - p1;
                    for (int ww = w0 + 1; ww < WPR && ((dsr == BIG) | (dcr == BIG)); ++ww) {
                        uint32_t word = ldcg_u32(&g_bits_T[ww * HH + r]);
                        if (dsr == BIG && word)  dsr = ((ww << 5) + __ffs(word) - 1) - p1;
                        uint32_t mcw = ~word;
                        if (dcr == BIG && mcw)   dcr = ((ww << 5) + __ffs(mcw) - 1) - p1;
                    }
                }
                int ds = min(dsl, dsr);               // nearest road col dist
                int dc = min(dcl, dcr);               // nearest non-road col dist
                int dr2 = (r - p0) * (r - p0);
                if (ds < 2048) best_nd = min(best_nd, dr2 + ds * ds);
                if (dc < 2048) best_dr = min(best_dr, dr2 + dc * dc);
            }
        }

        // ---- block min-reduce over 256 threads (8 warps) ----
        __shared__ int snd[8], sdr[8];
        best_nd = __reduce_min_sync(0xFFFFFFFFu, best_nd);
        best_dr = __reduce_min_sync(0xFFFFFFFFu, best_dr);
        if (lane == 0) { snd[wid] = best_nd; sdr[wid] = best_dr; }
        __syncthreads();

        if (tid == 0) {
            int a = snd[0], b = sdr[0];
#pragma unroll
            for (int k = 1; k < 8; ++k) { a = min(a, snd[k]); b = min(b, sdr[k]); }
            float L = 0.0f;
            if (!outside_frame) {
                // outside_road: replicate reference's validity masks exactly
                const bool rvm1 = (p0 >= 1);
                const bool rv0  = (p0 >= 1) && (p0 < HH);
                const bool cvm1 = (p1 >= 1);
                const bool cv0  = (p1 >= 1) && (p1 < WW);
                const bool outside_road =
                    (rvm1 && cvm1 && bit_at(p0 - 1, p1 - 1)) ||
                    (rvm1 && cv0  && bit_at(p0 - 1, p1    )) ||
                    (rv0  && cvm1 && bit_at(p0,     p1 - 1)) ||
                    (rv0  && cv0  && bit_at(p0,     p1    ));
                if (outside_road) {
                    // exp(sqrt(min_dr)*ln2/40) - 1 == 2^(sqrt(min_dr)/40) - 1
                    L = exp2f(sqrtf((float)b) * (1.0f / 40.0f)) - 1.0f;
                } else {
                    L = expf(-(float)a * (1.0f / 21.7f));
                }
            }
            g_loss[cta] = L;
        }
        __syncthreads();
    }

    // ============== finalize ticket: ALL CTAs arrive ========================
    // Every CTA arrives AFTER passing the g_sync spin, so the last arriver may
    // safely reset g_sync (nobody can still be spinning on it).
    __shared__ bool isLast;
    if (tid == 0) {
        __threadfence();             // point CTAs: g_loss write visible first
        unsigned prev = atomicAdd(&g_cnt, 1u);
        isLast = (prev == (unsigned)(CTAS - 1));
        if (isLast) __threadfence(); // acquire before reading g_loss
    }
    __syncthreads();

    // ---- last CTA: deterministic fixed-order reduction -> mean, reset ctrs ----
    if (isLast) {
        float v = 0.0f;
        for (int t = tid; t < N; t += TPB)
            v += __int_as_float((int)ldcg_u32((const uint32_t*)&g_loss[t]));
#pragma unroll
        for (int o = 16; o; o >>= 1) v += __shfl_down_sync(0xFFFFFFFFu, v, o);
        __shared__ float ws[8];
        if (lane == 0) ws[wid] = v;
        __syncthreads();
        if (tid == 0) {
            float s = 0.0f;
#pragma unroll
            for (int w = 0; w < 8; ++w) s += ws[w];
            out[0] = s / (float)N;
            g_sync = 0u;             // safe: all CTAs already past the spin
            g_cnt  = 0u;             // self-reset for next graph replay
        }
    }
}

extern "C" void kernel_launch(void* const* d_in, const int* in_sizes, int n_in,
                              void* d_out, int out_size) {
    const float* hd_map = (const float*)d_in[0];
    const int*   pred   = (const int*)d_in[1];
    float*       out    = (float*)d_out;
    const int N = in_sizes[1] / 2;   // 128

    fused_kernel<<<CTAS, TPB>>>((const float4*)hd_map, pred, out, N);
}

// round 9
// speedup vs baseline: 1.9692x; 1.8385x over previous
#include <cuda_runtime.h>
#include <cstdint>

#define HH 1024
#define WW 1024
#define TPB 256
#define R0  16          // initial window radius; P(insufficient) ~ e^-131

// Scratch (no allocations allowed)
__device__ float    g_loss[1024];
__device__ unsigned g_cnt;          // finalize ticket (self-resetting)

__device__ __forceinline__ int map_bit(const float* __restrict__ m, int r, int c) {
    r = min(max(r, 0), HH - 1);
    c = min(max(c, 0), WW - 1);
    return (__ldg(&m[r * WW + c]) != 0.0f) ? 1 : 0;
}

// One CTA per point: exact nearest-set / nearest-clear via windowed search with
// proof-of-optimality (found d^2 <= R^2 => nothing outside the window can beat it).
__global__ void __launch_bounds__(TPB) road_kernel(const float* __restrict__ map,
                                                   const int*   __restrict__ pred,
                                                   float*       __restrict__ out,
                                                   int N) {
    const int i    = blockIdx.x;
    const int tid  = threadIdx.x;
    const int lane = tid & 31;
    const int wid  = tid >> 5;

    const int p0 = __ldg(&pred[2 * i]);
    const int p1 = __ldg(&pred[2 * i + 1]);
    // outside_frame uses strict > H / > W (matches reference)
    const bool outside_frame = (p0 < 0) | (p0 > HH) | (p1 < 0) | (p1 > WW);

    __shared__ int swnd[8], swdr[8];
    __shared__ int s_nd, s_dr;
    int best_nd = 0x7FFFFFFF, best_dr = 0x7FFFFFFF;

    if (!outside_frame) {                       // block-uniform branch
        int R = R0;
        for (;;) {                              // block-uniform doubling loop
            const int r0 = max(p0 - R, 0), r1 = min(p0 + R, HH - 1);
            const int c0 = max(p1 - R, 0), c1 = min(p1 + R, WW - 1);
            const int nc = c1 - c0 + 1;
            const int total = (r1 - r0 + 1) * nc;

            int bn = 0x7FFFFFFF, bd = 0x7FFFFFFF;
            if (total <= 5 * TPB) {
                // Fast path (R=16 always lands here): 5 predicated, independent,
                // front-batched loads per thread -> single memory-latency round.
                float v[5]; int d2v[5]; bool ok[5];
#pragma unroll
                for (int u = 0; u < 5; ++u) {
                    int idx = tid + u * TPB;
                    ok[u] = (idx < total);
                    int id  = ok[u] ? idx : 0;
                    int rr  = id / nc, cc = id - rr * nc;
                    int r = r0 + rr, c = c0 + cc;
                    d2v[u] = (r - p0) * (r - p0) + (c - p1) * (c - p1);
                    v[u] = __ldg(&map[r * WW + c]);
                }
#pragma unroll
                for (int u = 0; u < 5; ++u) {
                    if (ok[u]) {
                        if (v[u] != 0.0f) bn = min(bn, d2v[u]);
                        else              bd = min(bd, d2v[u]);
                    }
                }
            } else {
                // Generic fallback (exactness guarantee; effectively never runs).
                for (int idx = tid; idx < total; idx += TPB) {
                    int rr = idx / nc, cc = idx - rr * nc;
                    int r = r0 + rr, c = c0 + cc;
                    float v = __ldg(&map[r * WW + c]);
                    int d2 = (r - p0) * (r - p0) + (c - p1) * (c - p1);
                    if (v != 0.0f) bn = min(bn, d2);
                    else           bd = min(bd, d2);
                }
            }

            // ---- block min-reduce (8 warps) ----
            bn = __reduce_min_sync(0xFFFFFFFFu, bn);
            bd = __reduce_min_sync(0xFFFFFFFFu, bd);
            if (lane == 0) { swnd[wid] = bn; swdr[wid] = bd; }
            __syncthreads();
            if (tid == 0) {
                int a = swnd[0], b = swdr[0];
#pragma unroll
                for (int k = 1; k < 8; ++k) { a = min(a, swnd[k]); b = min(b, swdr[k]); }
                s_nd = a; s_dr = b;
            }
            __syncthreads();
            best_nd = s_nd; best_dr = s_dr;

            // Proof: window covers every cell with max(|dr|,|dc|) <= R, so any
            // cell outside has d^2 > R^2. If both found mins are <= R^2, done.
            const long long R2 = (long long)R * (long long)R;
            const bool proven = ((long long)best_nd <= R2) && ((long long)best_dr <= R2);
            if (proven || R >= 1024) break;     // R>=1024 => window was full map
            R <<= 1;
            __syncthreads();                    // shared reuse hazard
        }
    }

    // ---- loss (thread 0), publish, ticket ----
    __shared__ bool isLast;
    if (tid == 0) {
        float L = 0.0f;
        if (!outside_frame) {
            // outside_road: replicate reference's validity masks exactly
            const bool rvm1 = (p0 >= 1);
            const bool rv0  = (p0 >= 1) && (p0 < HH);
            const bool cvm1 = (p1 >= 1);
            const bool cv0  = (p1 >= 1) && (p1 < WW);
            const bool outside_road =
                (rvm1 && cvm1 && map_bit(map, p0 - 1, p1 - 1)) ||
                (rvm1 && cv0  && map_bit(map, p0 - 1, p1    )) ||
                (rv0  && cvm1 && map_bit(map, p0,     p1 - 1)) ||
                (rv0  && cv0  && map_bit(map, p0,     p1    ));
            if (outside_road) {
                // exp(sqrt(min_dr)*ln2/40) - 1 == 2^(sqrt(min_dr)/40) - 1
                L = exp2f(sqrtf((float)best_dr) * (1.0f / 40.0f)) - 1.0f;
            } else {
                L = expf(-(float)best_nd * (1.0f / 21.7f));
            }
        }
        g_loss[i] = L;
        __threadfence();
        unsigned prev = atomicAdd(&g_cnt, 1u);
        isLast = (prev == (unsigned)(gridDim.x - 1));
        if (isLast) __threadfence();            // acquire before reading g_loss
    }
    __syncthreads();

    // ---- last CTA: deterministic fixed-order reduction -> mean, reset ticket ----
    if (isLast) {
        float v = (tid < N) ? g_loss[tid] : 0.0f;
#pragma unroll
        for (int o = 16; o; o >>= 1) v += __shfl_down_sync(0xFFFFFFFFu, v, o);
        __shared__ float ws[8];
        if (lane == 0) ws[wid] = v;
        __syncthreads();
        if (tid == 0) {
            float s = 0.0f;
#pragma unroll
            for (int w = 0; w < 8; ++w) s += ws[w];
            out[0] = s / (float)N;
            g_cnt = 0u;                         // self-reset for next graph replay
        }
    }
}

extern "C" void kernel_launch(void* const* d_in, const int* in_sizes, int n_in,
                              void* d_out, int out_size) {
    const float* hd_map = (const float*)d_in[0];
    const int*   pred   = (const int*)d_in[1];
    float*       out    = (float*)d_out;
    const int N = in_sizes[1] / 2;   // 128

    road_kernel<<<N, TPB>>>(hd_map, pred, out, N);
}

// round 10
// speedup vs baseline: 2.0000x; 1.0156x over previous
#include <cuda_runtime.h>
#include <cstdint>

#define HH 1024
#define WW 1024
#define TPB   256          // 8 warps per CTA
#define NCTA  16           // 16 CTAs x 8 warps = 128 warps = one per point
#define R0    8            // initial window radius; P(fallback) ~ 1e-12 per point
#define D0    (2 * R0 + 1) // 17
#define CELLS (D0 * D0)    // 289
#define LPL   10           // loads per lane: ceil(289/32)

// Scratch (no allocations allowed)
__device__ float    g_part[NCTA];   // per-CTA partial sums
__device__ unsigned g_cnt;          // finalize ticket (self-resetting)

__device__ __forceinline__ int map_bit(const float* __restrict__ m, int r, int c) {
    r = min(max(r, 0), HH - 1);
    c = min(max(c, 0), WW - 1);
    return (__ldg(&m[r * WW + c]) != 0.0f) ? 1 : 0;
}

__global__ void __launch_bounds__(TPB) road_kernel(const float* __restrict__ map,
                                                   const int*   __restrict__ pred,
                                                   float*       __restrict__ out,
                                                   int N) {
    const int tid  = threadIdx.x;
    const int cta  = blockIdx.x;
    const int lane = tid & 31;
    const int wid  = tid >> 5;

    float wsum = 0.0f;   // this warp's accumulated loss (usually 1 point)

    // Each warp handles points wp = cta*8 + wid, stepping by 128.
    for (int wp = cta * 8 + wid; wp < N; wp += NCTA * 8) {
        const int p0 = __ldg(&pred[2 * wp]);        // converged broadcast load
        const int p1 = __ldg(&pred[2 * wp + 1]);
        // outside_frame uses strict > H / > W (matches reference)
        const bool outside_frame = (p0 < 0) | (p0 > HH) | (p1 < 0) | (p1 > WW);
        if (outside_frame) continue;                // contributes 0

        int best_nd = 0x7FFFFFFF, best_dr = 0x7FFFFFFF;

        // ---------- fast path: fixed 17x17 window, clamp-duplicated ----------
        {
            float v[LPL]; int d2[LPL];
#pragma unroll
            for (int u = 0; u < LPL; ++u) {
                unsigned idx = (unsigned)min(lane + u * 32, CELLS - 1); // dup tail cell
                int rr = (int)(idx / (unsigned)D0);
                int cc = (int)(idx - (unsigned)rr * (unsigned)D0);
                int r = min(max(p0 - R0 + rr, 0), HH - 1);   // clamped cell
                int c = min(max(p1 - R0 + cc, 0), WW - 1);   // (dups harmless for min)
                d2[u] = (r - p0) * (r - p0) + (c - p1) * (c - p1);
                v[u]  = __ldg(&map[r * WW + c]);             // independent loads, MLP=10
            }
#pragma unroll
            for (int u = 0; u < LPL; ++u) {
                if (v[u] != 0.0f) best_nd = min(best_nd, d2[u]);
                else              best_dr = min(best_dr, d2[u]);
            }
        }
        best_nd = __reduce_min_sync(0xFFFFFFFFu, best_nd);
        best_dr = __reduce_min_sync(0xFFFFFFFFu, best_dr);

        // ---------- exactness proof + warp-autonomous doubling fallback ------
        // Window covers every in-bounds cell with Chebyshev dist <= R, so any
        // uncovered cell has d^2 > R^2. If both mins <= R^2 they are exact.
        int R = R0;
        while (!((best_nd <= R * R) && (best_dr <= R * R)) && R < 1024) {
            R <<= 1;
            const int r0 = max(p0 - R, 0), r1 = min(p0 + R, HH - 1);
            const int c0 = max(p1 - R, 0), c1 = min(p1 + R, WW - 1);
            const int nc = c1 - c0 + 1;
            const int total = (r1 - r0 + 1) * nc;
            int bn = 0x7FFFFFFF, bd = 0x7FFFFFFF;
            for (int idx = lane; idx < total; idx += 32) {
                int rr = idx / nc, cc = idx - rr * nc;
                int r = r0 + rr, c = c0 + cc;
                float v = __ldg(&map[r * WW + c]);
                int d2 = (r - p0) * (r - p0) + (c - p1) * (c - p1);
                if (v != 0.0f) bn = min(bn, d2);
                else           bd = min(bd, d2);
            }
            best_nd = __reduce_min_sync(0xFFFFFFFFu, bn);
            best_dr = __reduce_min_sync(0xFFFFFFFFu, bd);
        }

        // ---------- loss on lane 0 ----------
        if (lane == 0) {
            // outside_road: replicate reference's validity masks exactly
            const bool rvm1 = (p0 >= 1);
            const bool rv0  = (p0 >= 1) && (p0 < HH);
            const bool cvm1 = (p1 >= 1);
            const bool cv0  = (p1 >= 1) && (p1 < WW);
            const bool outside_road =
                (rvm1 && cvm1 && map_bit(map, p0 - 1, p1 - 1)) ||
                (rvm1 && cv0  && map_bit(map, p0 - 1, p1    )) ||
                (rv0  && cvm1 && map_bit(map, p0,     p1 - 1)) ||
                (rv0  && cv0  && map_bit(map, p0,     p1    ));
            if (outside_road) {
                // exp(sqrt(min_dr)*ln2/40) - 1 == 2^(sqrt(min_dr)/40) - 1
                wsum += exp2f(sqrtf((float)best_dr) * (1.0f / 40.0f)) - 1.0f;
            } else {
                wsum += expf(-(float)best_nd * (1.0f / 21.7f));
            }
        }
    }

    // ---------- CTA partial: fixed-order sum of 8 warp losses ----------
    __shared__ float wl[8];
    if (lane == 0) wl[wid] = wsum;
    __syncthreads();

    __shared__ bool isLast;
    if (tid == 0) {
        float p = 0.0f;
#pragma unroll
        for (int k = 0; k < 8; ++k) p += wl[k];
        g_part[cta] = p;
        __threadfence();
        unsigned prev = atomicAdd(&g_cnt, 1u);
        isLast = (prev == (unsigned)(NCTA - 1));
        if (isLast) __threadfence();            // acquire before reading g_part
    }
    __syncthreads();

    // ---------- last CTA: deterministic fixed-order final sum ----------
    if (isLast && tid == 0) {
        float s = 0.0f;
#pragma unroll
        for (int k = 0; k < NCTA; ++k) {
            float pv;
            asm volatile("ld.global.cg.f32 %0, [%1];" : "=f"(pv) : "l"(&g_part[k]));
            s += pv;
        }
        out[0] = s / (float)N;
        g_cnt = 0u;                             // self-reset for next graph replay
    }
}

extern "C" void kernel_launch(void* const* d_in, const int* in_sizes, int n_in,
                              void* d_out, int out_size) {
    const float* hd_map = (const float*)d_in[0];
    const int*   pred   = (const int*)d_in[1];
    float*       out    = (float*)d_out;
    const int N = in_sizes[1] / 2;   // 128

    road_kernel<<<NCTA, TPB>>>(hd_map, pred, out, N);
}